// round 3
// baseline (speedup 1.0000x reference)
#include <cuda_runtime.h>
#include <math.h>

#define N_NODES 50000
#define HIDDEN  128
#define MSG     64
#define NGATE   256   // 4*MSG
#define NT      8     // nodes per tile in node_kernel
#define CAP     128   // per-node edge-slot capacity (deg ~ Poisson(16); P(>=128) ~ 1e-80)

// ---- static scratch (no allocation APIs allowed) --------------------------
__device__ int   g_cnt0[N_NODES];
__device__ int   g_cnt1[N_NODES];
__device__ int   g_list0[(size_t)N_NODES * CAP];
__device__ int   g_list1[(size_t)N_NODES * CAP];
__device__ float g_rst[(size_t)N_NODES * HIDDEN];

// ---------------------------------------------------------------------------
// Kernel 1: zero the slot counters
// ---------------------------------------------------------------------------
__global__ void zero_kernel() {
    int i = blockIdx.x * blockDim.x + threadIdx.x;
    if (i < N_NODES) { g_cnt0[i] = 0; g_cnt1[i] = 0; }
}

// ---------------------------------------------------------------------------
// Kernel 2: bucket edges by destination (both etypes in one grid).
// One int atomic per edge (spread over 100k addresses -> near LSU floor).
// ---------------------------------------------------------------------------
__global__ void scatter_kernel(const int* __restrict__ src0, const int* __restrict__ dst0, int E0,
                               const int* __restrict__ src1, const int* __restrict__ dst1, int E1) {
    int e = blockIdx.x * blockDim.x + threadIdx.x;
    if (e < E0) {
        int d = dst0[e];
        int pos = atomicAdd(&g_cnt0[d], 1);
        if (pos < CAP) g_list0[(size_t)d * CAP + pos] = src0[e];
    } else if (e < E0 + E1) {
        int e1 = e - E0;
        int d = dst1[e1];
        int pos = atomicAdd(&g_cnt1[d], 1);
        if (pos < CAP) g_list1[(size_t)d * CAP + pos] = src1[e1];
    }
}

// ---------------------------------------------------------------------------
// Kernel 3: warp-per-node aggregation. Lane l owns float4 chunk l of the
// 128-wide row. Edge src indices are loaded 32-at-a-time (coalesced) and
// broadcast via shfl; the feat row gathers are 512B/warp coalesced and hit
// L2 (feat = 25.6MB, fully L2-resident). Writes
// rst = (mean0 + mean1) / n_active directly.
// ---------------------------------------------------------------------------
__global__ void agg_kernel(const float* __restrict__ feat) {
    int v    = (blockIdx.x * blockDim.x + threadIdx.x) >> 5;
    int lane = threadIdx.x & 31;
    if (v >= N_NODES) return;

    const float4* f4 = (const float4*)feat;

    int c0 = g_cnt0[v];
    int c1 = g_cnt1[v];
    int n0 = min(c0, CAP);
    int n1 = min(c1, CAP);

    float4 s0 = make_float4(0.f, 0.f, 0.f, 0.f);
    float4 s1 = make_float4(0.f, 0.f, 0.f, 0.f);

    const int* l0 = g_list0 + (size_t)v * CAP;
    for (int base = 0; base < n0; base += 32) {
        int sl = (base + lane < n0) ? l0[base + lane] : 0;
        int m = min(32, n0 - base);
        for (int j = 0; j < m; j++) {
            int s = __shfl_sync(0xffffffffu, sl, j);
            float4 f = f4[(size_t)s * (HIDDEN / 4) + lane];
            s0.x += f.x; s0.y += f.y; s0.z += f.z; s0.w += f.w;
        }
    }
    const int* l1 = g_list1 + (size_t)v * CAP;
    for (int base = 0; base < n1; base += 32) {
        int sl = (base + lane < n1) ? l1[base + lane] : 0;
        int m = min(32, n1 - base);
        for (int j = 0; j < m; j++) {
            int s = __shfl_sync(0xffffffffu, sl, j);
            float4 f = f4[(size_t)s * (HIDDEN / 4) + lane];
            s1.x += f.x; s1.y += f.y; s1.z += f.z; s1.w += f.w;
        }
    }

    float inv0 = 1.f / fmaxf((float)c0, 1.f);
    float inv1 = 1.f / fmaxf((float)c1, 1.f);
    float na   = fmaxf((c0 > 0 ? 1.f : 0.f) + (c1 > 0 ? 1.f : 0.f), 1.f);
    float inva = 1.f / na;

    float4 r;
    r.x = (s0.x * inv0 + s1.x * inv1) * inva;
    r.y = (s0.y * inv0 + s1.y * inv1) * inva;
    r.z = (s0.z * inv0 + s1.z * inv1) * inva;
    r.w = (s0.w * inv0 + s1.w * inv1) * inva;
    ((float4*)g_rst)[(size_t)v * (HIDDEN / 4) + lane] = r;
}

// ---------------------------------------------------------------------------
// Kernel 4: fused GEMM + LSTM cell. 256 threads = 256 gate rows, NT=8 nodes
// per tile, persistent 148 blocks. Weights in SMEM row-major padded
// (stride 129 / 65) so the per-k read W[t][k] is conflict-free AND the
// global load is coalesced. Features packed [k][node] so node-pairs are
// 8-byte operands for packed fma.rn.f32x2 (FFMA2 -> 2x fp32 FMA rate).
// FMA-pipe bound: 192 k-iters x 4 FFMA2 = 16 cyc/k per SMSP at 2 warps/SMSP.
// ---------------------------------------------------------------------------
__global__ void __launch_bounds__(256, 1)
node_kernel(const float* __restrict__ feat,
            const float* __restrict__ W_ih,
            const float* __restrict__ W_hh,
            const float* __restrict__ b_ih,
            const float* __restrict__ b_hh,
            float* __restrict__ out) {
    extern __shared__ float smem[];
    float* Wih_sh   = smem;                      // 256 * 129
    float* Whh_sh   = Wih_sh + 256 * 129;        // 256 * 65
    float* b_sh     = Whh_sh + 256 * 65;         // 256
    float* feat_sh  = b_sh + 256;                // 128 * 8  [k][node], 16B aligned
    float* rst_sh   = feat_sh + HIDDEN * NT;     // 128 * 8  [k][node], 16B aligned
    float* gates_sh = rst_sh + HIDDEN * NT;      // 8 * 256  [node][gate]

    int t = threadIdx.x;  // gate index 0..255

    // one-time weight staging (coalesced global, conflict-free smem reads later)
    for (int idx = t; idx < NGATE * HIDDEN; idx += 256) {
        int g = idx >> 7, k = idx & 127;
        Wih_sh[g * 129 + k] = W_ih[idx];
    }
    for (int idx = t; idx < NGATE * MSG; idx += 256) {
        int g = idx >> 6, k = idx & 63;
        Whh_sh[g * 65 + k] = W_hh[idx];
    }
    b_sh[t] = b_ih[t] + b_hh[t];
    __syncthreads();

    const float* wrow_ih = Wih_sh + t * 129;
    const float* wrow_hh = Whh_sh + t * 65;

    const int ntiles = N_NODES / NT;  // 6250 exactly
    for (int tile = blockIdx.x; tile < ntiles; tile += gridDim.x) {
        int node0 = tile * NT;

        // stage feat + rst in [k][node] packed layout (coalesced global loads)
        for (int idx = t; idx < NT * HIDDEN; idx += 256) {
            int n = idx >> 7, k = idx & 127;
            size_t v = (size_t)(node0 + n);
            feat_sh[k * NT + n] = feat[v * HIDDEN + k];
            rst_sh[k * NT + n]  = g_rst[v * HIDDEN + k];
        }
        __syncthreads();

        // acc[j] = packed gate value for node pair (2j, 2j+1)
        unsigned long long acc[4];
        {
            float b = b_sh[t];
            unsigned long long bp;
            asm("mov.b64 %0, {%1, %1};" : "=l"(bp) : "f"(b));
            acc[0] = bp; acc[1] = bp; acc[2] = bp; acc[3] = bp;
        }

        // gates += feat @ W_ih^T
        #pragma unroll 8
        for (int k = 0; k < HIDDEN; k++) {
            float w = wrow_ih[k];
            unsigned long long wp;
            asm("mov.b64 %0, {%1, %1};" : "=l"(wp) : "f"(w));
            const ulonglong2* fp = (const ulonglong2*)&feat_sh[k * NT];
            ulonglong2 fab = fp[0];  // nodes 0-1, 2-3 (broadcast LDS.128)
            ulonglong2 fcd = fp[1];  // nodes 4-5, 6-7
            asm("fma.rn.f32x2 %0, %1, %2, %0;" : "+l"(acc[0]) : "l"(wp), "l"(fab.x));
            asm("fma.rn.f32x2 %0, %1, %2, %0;" : "+l"(acc[1]) : "l"(wp), "l"(fab.y));
            asm("fma.rn.f32x2 %0, %1, %2, %0;" : "+l"(acc[2]) : "l"(wp), "l"(fcd.x));
            asm("fma.rn.f32x2 %0, %1, %2, %0;" : "+l"(acc[3]) : "l"(wp), "l"(fcd.y));
        }
        // gates += G_t @ W_hh^T   (G_t = rst[:, 0:64])
        #pragma unroll 8
        for (int k = 0; k < MSG; k++) {
            float w = wrow_hh[k];
            unsigned long long wp;
            asm("mov.b64 %0, {%1, %1};" : "=l"(wp) : "f"(w));
            const ulonglong2* rp = (const ulonglong2*)&rst_sh[k * NT];
            ulonglong2 rab = rp[0];
            ulonglong2 rcd = rp[1];
            asm("fma.rn.f32x2 %0, %1, %2, %0;" : "+l"(acc[0]) : "l"(wp), "l"(rab.x));
            asm("fma.rn.f32x2 %0, %1, %2, %0;" : "+l"(acc[1]) : "l"(wp), "l"(rab.y));
            asm("fma.rn.f32x2 %0, %1, %2, %0;" : "+l"(acc[2]) : "l"(wp), "l"(rcd.x));
            asm("fma.rn.f32x2 %0, %1, %2, %0;" : "+l"(acc[3]) : "l"(wp), "l"(rcd.y));
        }

        #pragma unroll
        for (int j = 0; j < 4; j++) {
            float lo, hi;
            asm("mov.b64 {%0, %1}, %2;" : "=f"(lo), "=f"(hi) : "l"(acc[j]));
            gates_sh[(2 * j) * NGATE + t]     = lo;
            gates_sh[(2 * j + 1) * NGATE + t] = hi;
        }
        __syncthreads();

        // LSTM nonlinearity + output (out = [h1, c1], each MSG wide)
        for (int idx = t; idx < NT * MSG; idx += 256) {
            int n = idx >> 6, j = idx & 63;
            size_t v = (size_t)(node0 + n);
            float gi = gates_sh[n * NGATE + j];
            float gf = gates_sh[n * NGATE + 64 + j];
            float gg = gates_sh[n * NGATE + 128 + j];
            float go = gates_sh[n * NGATE + 192 + j];
            float R  = rst_sh[(64 + j) * NT + n];
            float si = 1.f / (1.f + __expf(-gi));
            float sf = 1.f / (1.f + __expf(-gf));
            float so = 1.f / (1.f + __expf(-go));
            float c1v = sf * R + si * tanhf(gg);
            float h1v = so * tanhf(c1v);
            out[v * HIDDEN + j]       = h1v;
            out[v * HIDDEN + MSG + j] = c1v;
        }
        __syncthreads();
    }
}

// ---------------------------------------------------------------------------
static const int NODE_SMEM = (256 * 129 + 256 * 65 + 256
                              + HIDDEN * NT + HIDDEN * NT + NT * NGATE)
                             * (int)sizeof(float);  // 216,064 B (< 227KB cap)

extern "C" void kernel_launch(void* const* d_in, const int* in_sizes, int n_in,
                              void* d_out, int out_size) {
    const float* feat = (const float*)d_in[0];
    const int*   src0 = (const int*)d_in[1];
    const int*   dst0 = (const int*)d_in[2];
    const int*   src1 = (const int*)d_in[3];
    const int*   dst1 = (const int*)d_in[4];
    const float* W_ih = (const float*)d_in[5];
    const float* W_hh = (const float*)d_in[6];
    const float* b_ih = (const float*)d_in[7];
    const float* b_hh = (const float*)d_in[8];
    float* out = (float*)d_out;

    int E0 = in_sizes[1];
    int E1 = in_sizes[3];

    zero_kernel<<<(N_NODES + 255) / 256, 256>>>();

    int totalE = E0 + E1;
    scatter_kernel<<<(totalE + 255) / 256, 256>>>(src0, dst0, E0, src1, dst1, E1);

    agg_kernel<<<(N_NODES * 32 + 255) / 256, 256>>>(feat);

    cudaFuncSetAttribute(node_kernel,
                         cudaFuncAttributeMaxDynamicSharedMemorySize, NODE_SMEM);
    node_kernel<<<148, 256, NODE_SMEM>>>(feat, W_ih, W_hh, b_ih, b_hh, out);
}

// round 15
// speedup vs baseline: 1.7587x; 1.7587x over previous
#include <cuda_runtime.h>
#include <math.h>

#define N_NODES 50000
#define HIDDEN  128
#define MSG     64
#define NGATE   256   // 4*MSG
#define CAP     128   // per-node edge-slot capacity (deg ~ Poisson(16); P(>=128) ~ 1e-80)

#define KTOT    192   // concatenated K: 128 (feat) + 64 (G = rst[:, :64])
#define NT      32    // nodes per block tile
#define NTILES  ((N_NODES + NT - 1) / NT)   // 1563

// ---- static scratch (no allocation APIs allowed) --------------------------
__device__ int   g_cnt0[N_NODES];
__device__ int   g_cnt1[N_NODES];
__device__ int   g_list0[(size_t)N_NODES * CAP];
__device__ int   g_list1[(size_t)N_NODES * CAP];
__device__ float g_rst[(size_t)N_NODES * HIDDEN];

// ---------------------------------------------------------------------------
// Kernel 1: zero the slot counters
// ---------------------------------------------------------------------------
__global__ void zero_kernel() {
    int i = blockIdx.x * blockDim.x + threadIdx.x;
    if (i < N_NODES) { g_cnt0[i] = 0; g_cnt1[i] = 0; }
}

// ---------------------------------------------------------------------------
// Kernel 2: bucket edges by destination (both etypes in one grid).
// ---------------------------------------------------------------------------
__global__ void scatter_kernel(const int* __restrict__ src0, const int* __restrict__ dst0, int E0,
                               const int* __restrict__ src1, const int* __restrict__ dst1, int E1) {
    int e = blockIdx.x * blockDim.x + threadIdx.x;
    if (e < E0) {
        int d = dst0[e];
        int pos = atomicAdd(&g_cnt0[d], 1);
        if (pos < CAP) g_list0[(size_t)d * CAP + pos] = src0[e];
    } else if (e < E0 + E1) {
        int e1 = e - E0;
        int d = dst1[e1];
        int pos = atomicAdd(&g_cnt1[d], 1);
        if (pos < CAP) g_list1[(size_t)d * CAP + pos] = src1[e1];
    }
}

// ---------------------------------------------------------------------------
// Kernel 3: warp-per-node aggregation (measured fast in R3; unchanged).
// ---------------------------------------------------------------------------
__global__ void agg_kernel(const float* __restrict__ feat) {
    int v    = (blockIdx.x * blockDim.x + threadIdx.x) >> 5;
    int lane = threadIdx.x & 31;
    if (v >= N_NODES) return;

    const float4* f4 = (const float4*)feat;

    int c0 = g_cnt0[v];
    int c1 = g_cnt1[v];
    int n0 = min(c0, CAP);
    int n1 = min(c1, CAP);

    float4 s0 = make_float4(0.f, 0.f, 0.f, 0.f);
    float4 s1 = make_float4(0.f, 0.f, 0.f, 0.f);

    const int* l0 = g_list0 + (size_t)v * CAP;
    for (int base = 0; base < n0; base += 32) {
        int sl = (base + lane < n0) ? l0[base + lane] : 0;
        int m = min(32, n0 - base);
        for (int j = 0; j < m; j++) {
            int s = __shfl_sync(0xffffffffu, sl, j);
            float4 f = f4[(size_t)s * (HIDDEN / 4) + lane];
            s0.x += f.x; s0.y += f.y; s0.z += f.z; s0.w += f.w;
        }
    }
    const int* l1 = g_list1 + (size_t)v * CAP;
    for (int base = 0; base < n1; base += 32) {
        int sl = (base + lane < n1) ? l1[base + lane] : 0;
        int m = min(32, n1 - base);
        for (int j = 0; j < m; j++) {
            int s = __shfl_sync(0xffffffffu, sl, j);
            float4 f = f4[(size_t)s * (HIDDEN / 4) + lane];
            s1.x += f.x; s1.y += f.y; s1.z += f.z; s1.w += f.w;
        }
    }

    float inv0 = 1.f / fmaxf((float)c0, 1.f);
    float inv1 = 1.f / fmaxf((float)c1, 1.f);
    float na   = fmaxf((c0 > 0 ? 1.f : 0.f) + (c1 > 0 ? 1.f : 0.f), 1.f);
    float inva = 1.f / na;

    float4 r;
    r.x = (s0.x * inv0 + s1.x * inv1) * inva;
    r.y = (s0.y * inv0 + s1.y * inv1) * inva;
    r.z = (s0.z * inv0 + s1.z * inv1) * inva;
    r.w = (s0.w * inv0 + s1.w * inv1) * inva;
    ((float4*)g_rst)[(size_t)v * (HIDDEN / 4) + lane] = r;
}

// fast tanh via __expf: exact saturation at +/-inf, ~1e-6 rel error
__device__ __forceinline__ float fast_tanh(float x) {
    float e = __expf(2.f * x);
    return 1.f - __fdividef(2.f, e + 1.f);
}
__device__ __forceinline__ float fast_sigmoid(float x) {
    return __fdividef(1.f, 1.f + __expf(-x));
}

// ---------------------------------------------------------------------------
// Kernel 4 (v2.1): register-tiled fused GEMM + LSTM.
//
// Block: 256 threads, persistent over 1563 tiles of NT=32 nodes.
// Thread (j = tid&63, ngrp = tid>>6): gates {j, j+64, j+128, j+192} (full
// i/f/g/o set) x nodes [ngrp*8, ngrp*8+8) -> 32 accs as 16 f32x2 pairs.
//
// SMEM:
//   Wt[k][4j+q]  k=0..191 interleaved  -> one conflict-free LDS.128 per k
//                gives all 4 gate weights of thread j.
//   A [k][n]     k=0..191 = [feat | G], stride 32 -> warp-broadcast LDS.128.
//   R [j][n]     stride 33 -> conflict-free epilogue reads of rst[:,64+j].
//
// Per-k issues/warp: 3 LDS.128 + 8 MOV(pack) + 16 FFMA2 = 27 issues vs
// 32 fma-pipe cycles -> FMA-bound with slack. fp32 roofline floor ~72us.
// ---------------------------------------------------------------------------
__global__ void __launch_bounds__(256, 1)
node_kernel(const float* __restrict__ feat,
            const float* __restrict__ W_ih,
            const float* __restrict__ W_hh,
            const float* __restrict__ b_ih,
            const float* __restrict__ b_hh,
            float* __restrict__ out) {
    extern __shared__ float smem[];
    float* Wt  = smem;                       // 192*256 = 49152 floats
    float* Ash = Wt + KTOT * NGATE;          // 192*32  =  6144 floats
    float* Rsh = Ash + KTOT * NT;            // 64*33   =  2112 floats

    const int tid  = threadIdx.x;
    const int j    = tid & 63;               // gate base index
    const int ngrp = tid >> 6;               // 0..3
    const int n0   = ngrp * 8;
    const int l    = tid & 31;               // staging lane -> node
    const int kq   = tid >> 5;               // staging k-quarter 0..7

    // ---- one-time weight staging (column-major: conflict-free STS) ------
    // Main loop reads Wt[k][col] with col = 4j+q == W_cat[j + 64q][k],
    // so column col holds gate row grow = 64*(col&3) + (col>>2).
    {
        int col  = tid;
        int grow = 64 * (col & 3) + (col >> 2);
        #pragma unroll 8
        for (int k4 = 0; k4 < 48; k4++) {
            const float* src = (k4 < 32) ? (W_ih + (size_t)grow * HIDDEN + k4 * 4)
                                         : (W_hh + (size_t)grow * MSG + (k4 - 32) * 4);
            float4 w = *(const float4*)src;
            Wt[(4 * k4 + 0) * NGATE + col] = w.x;
            Wt[(4 * k4 + 1) * NGATE + col] = w.y;
            Wt[(4 * k4 + 2) * NGATE + col] = w.z;
            Wt[(4 * k4 + 3) * NGATE + col] = w.w;
        }
    }

    // per-thread bias (block lifetime), packed {b,b}
    unsigned long long bp[4];
    #pragma unroll
    for (int q = 0; q < 4; q++) {
        float b = b_ih[j + 64 * q] + b_hh[j + 64 * q];
        asm("mov.b64 %0, {%1, %1};" : "=l"(bp[q]) : "f"(b));
    }
    __syncthreads();

    const float4* feat4 = (const float4*)feat;
    const float4* rst4  = (const float4*)g_rst;

    for (int tile = blockIdx.x; tile < NTILES; tile += gridDim.x) {
        int node0 = tile * NT;

        // ---- stage A (k 0..191) and R (rst[:,64:]) --------------------
        // lane l -> node, so STS bank = l: conflict-free transpose.
        int v = node0 + l;
        if (v >= N_NODES) v = N_NODES - 1;   // clamp; epilogue guards writes
        #pragma unroll
        for (int c = 0; c < 64; c += 8) {
            int k4 = c + kq;                 // 0..63 float4 chunks of 256 cols
            float4 f = (k4 < 32) ? feat4[(size_t)v * 32 + k4]
                                 : rst4[(size_t)v * 32 + (k4 - 32)];
            if (k4 < 48) {
                Ash[(4 * k4 + 0) * NT + l] = f.x;
                Ash[(4 * k4 + 1) * NT + l] = f.y;
                Ash[(4 * k4 + 2) * NT + l] = f.z;
                Ash[(4 * k4 + 3) * NT + l] = f.w;
            } else {
                int jj = 4 * (k4 - 48);      // 0..60
                Rsh[(jj + 0) * 33 + l] = f.x;
                Rsh[(jj + 1) * 33 + l] = f.y;
                Rsh[(jj + 2) * 33 + l] = f.z;
                Rsh[(jj + 3) * 33 + l] = f.w;
            }
        }
        __syncthreads();

        // ---- main GEMM loop ------------------------------------------
        unsigned long long acc[4][4];        // [gate q][node-pair p]
        #pragma unroll
        for (int q = 0; q < 4; q++)
            #pragma unroll
            for (int p = 0; p < 4; p++) acc[q][p] = bp[q];

        const float* wptr = Wt + 4 * j;
        #pragma unroll 4
        for (int k = 0; k < KTOT; k++) {
            float4 w = *(const float4*)(wptr + k * NGATE);   // gates j+{0,64,128,192}
            unsigned long long wp0, wp1, wp2, wp3;
            asm("mov.b64 %0, {%1, %1};" : "=l"(wp0) : "f"(w.x));
            asm("mov.b64 %0, {%1, %1};" : "=l"(wp1) : "f"(w.y));
            asm("mov.b64 %0, {%1, %1};" : "=l"(wp2) : "f"(w.z));
            asm("mov.b64 %0, {%1, %1};" : "=l"(wp3) : "f"(w.w));
            ulonglong2 fab = *(const ulonglong2*)&Ash[k * NT + n0];      // nodes 0-3
            ulonglong2 fcd = *(const ulonglong2*)&Ash[k * NT + n0 + 4];  // nodes 4-7
            asm("fma.rn.f32x2 %0, %1, %2, %0;" : "+l"(acc[0][0]) : "l"(wp0), "l"(fab.x));
            asm("fma.rn.f32x2 %0, %1, %2, %0;" : "+l"(acc[0][1]) : "l"(wp0), "l"(fab.y));
            asm("fma.rn.f32x2 %0, %1, %2, %0;" : "+l"(acc[0][2]) : "l"(wp0), "l"(fcd.x));
            asm("fma.rn.f32x2 %0, %1, %2, %0;" : "+l"(acc[0][3]) : "l"(wp0), "l"(fcd.y));
            asm("fma.rn.f32x2 %0, %1, %2, %0;" : "+l"(acc[1][0]) : "l"(wp1), "l"(fab.x));
            asm("fma.rn.f32x2 %0, %1, %2, %0;" : "+l"(acc[1][1]) : "l"(wp1), "l"(fab.y));
            asm("fma.rn.f32x2 %0, %1, %2, %0;" : "+l"(acc[1][2]) : "l"(wp1), "l"(fcd.x));
            asm("fma.rn.f32x2 %0, %1, %2, %0;" : "+l"(acc[1][3]) : "l"(wp1), "l"(fcd.y));
            asm("fma.rn.f32x2 %0, %1, %2, %0;" : "+l"(acc[2][0]) : "l"(wp2), "l"(fab.x));
            asm("fma.rn.f32x2 %0, %1, %2, %0;" : "+l"(acc[2][1]) : "l"(wp2), "l"(fab.y));
            asm("fma.rn.f32x2 %0, %1, %2, %0;" : "+l"(acc[2][2]) : "l"(wp2), "l"(fcd.x));
            asm("fma.rn.f32x2 %0, %1, %2, %0;" : "+l"(acc[2][3]) : "l"(wp2), "l"(fcd.y));
            asm("fma.rn.f32x2 %0, %1, %2, %0;" : "+l"(acc[3][0]) : "l"(wp3), "l"(fab.x));
            asm("fma.rn.f32x2 %0, %1, %2, %0;" : "+l"(acc[3][1]) : "l"(wp3), "l"(fab.y));
            asm("fma.rn.f32x2 %0, %1, %2, %0;" : "+l"(acc[3][2]) : "l"(wp3), "l"(fcd.x));
            asm("fma.rn.f32x2 %0, %1, %2, %0;" : "+l"(acc[3][3]) : "l"(wp3), "l"(fcd.y));
        }

        // ---- epilogue: thread owns complete i/f/g/o per node ----------
        #pragma unroll
        for (int p = 0; p < 4; p++) {
            float gi0, gi1, gf0, gf1, gg0, gg1, go0, go1;
            asm("mov.b64 {%0, %1}, %2;" : "=f"(gi0), "=f"(gi1) : "l"(acc[0][p]));
            asm("mov.b64 {%0, %1}, %2;" : "=f"(gf0), "=f"(gf1) : "l"(acc[1][p]));
            asm("mov.b64 {%0, %1}, %2;" : "=f"(gg0), "=f"(gg1) : "l"(acc[2][p]));
            asm("mov.b64 {%0, %1}, %2;" : "=f"(go0), "=f"(go1) : "l"(acc[3][p]));
            #pragma unroll
            for (int h = 0; h < 2; h++) {
                int n  = 2 * p + h;
                int vv = node0 + n0 + n;
                if (vv < N_NODES) {
                    float gi = h ? gi1 : gi0;
                    float gf = h ? gf1 : gf0;
                    float gg = h ? gg1 : gg0;
                    float go = h ? go1 : go0;
                    float R  = Rsh[j * 33 + n0 + n];
                    float c1v = fast_sigmoid(gf) * R + fast_sigmoid(gi) * fast_tanh(gg);
                    float h1v = fast_sigmoid(go) * fast_tanh(c1v);
                    out[(size_t)vv * HIDDEN + j]       = h1v;
                    out[(size_t)vv * HIDDEN + MSG + j] = c1v;
                }
            }
        }
        __syncthreads();   // A/R reused next tile
    }
}

// ---------------------------------------------------------------------------
static const int NODE_SMEM = (KTOT * NGATE + KTOT * NT + 64 * 33)
                             * (int)sizeof(float);  // 229,632 B (< 232,448 B cap)

extern "C" void kernel_launch(void* const* d_in, const int* in_sizes, int n_in,
                              void* d_out, int out_size) {
    const float* feat = (const float*)d_in[0];
    const int*   src0 = (const int*)d_in[1];
    const int*   dst0 = (const int*)d_in[2];
    const int*   src1 = (const int*)d_in[3];
    const int*   dst1 = (const int*)d_in[4];
    const float* W_ih = (const float*)d_in[5];
    const float* W_hh = (const float*)d_in[6];
    const float* b_ih = (const float*)d_in[7];
    const float* b_hh = (const float*)d_in[8];
    float* out = (float*)d_out;

    int E0 = in_sizes[1];
    int E1 = in_sizes[3];

    zero_kernel<<<(N_NODES + 255) / 256, 256>>>();

    int totalE = E0 + E1;
    scatter_kernel<<<(totalE + 255) / 256, 256>>>(src0, dst0, E0, src1, dst1, E1);

    agg_kernel<<<(N_NODES * 32 + 255) / 256, 256>>>(feat);

    cudaFuncSetAttribute(node_kernel,
                         cudaFuncAttributeMaxDynamicSharedMemorySize, NODE_SMEM);
    node_kernel<<<148, 256, NODE_SMEM>>>(feat, W_ih, W_hh, b_ih, b_hh, out);
}